// round 10
// baseline (speedup 1.0000x reference)
#include <cuda_runtime.h>
#include <cstdint>
#include <cstddef>
#include <string.h>

// ---------------- problem constants ----------------
constexpr int B    = 8;
constexpr int T    = 32768;
constexpr int M    = B * T;          // 262144 points
constexpr int NP   = 3;
constexpr int RESO = 64;
constexpr int R2   = RESO * RESO;    // 4096
constexpr size_t NBINS = (size_t)B * NP * R2 * 128;   // 12,582,912
constexpr size_t NCNT  = (size_t)B * NP * R2;         // 98,304

typedef unsigned long long ull;

// ---------------- scratch (__device__ globals; no allocation) ----------------
__device__ float    g_x256[(size_t)M * 256];   // [net | pooled] concat buffer
__device__ float    g_tmp [(size_t)M * 128];   // n0 temp
__device__ float    g_dx  [(size_t)M * 128];   // dx temp
__device__ int      g_idx [3 * M];             // plane bin indices
__device__ unsigned g_hmax[B * 128];           // column max (float bits, >=0)
__device__ float    g_netpl[B * 128];
__device__ float    g_Cmat[B * NP * 12];       // (4,3) per plane
__device__ unsigned g_bins[NBINS];             // scatter-max (encoded) / scatter-add (float bits)
__device__ unsigned g_cnt [NCNT];              // float bits

// ---------------- helpers ----------------
__device__ __forceinline__ unsigned ford(float f) {
    unsigned u = __float_as_uint(f);
    return (f >= 0.f) ? (u | 0x80000000u) : ~u;
}
__device__ __forceinline__ float iford(unsigned u) {
    return (u & 0x80000000u) ? __uint_as_float(u & 0x7FFFFFFFu) : __uint_as_float(~u);
}

__device__ __forceinline__ void fma2(ull& acc, ull a, ull b) {
    asm("fma.rn.f32x2 %0, %1, %2, %0;" : "+l"(acc) : "l"(a), "l"(b));
}
__device__ __forceinline__ ull pack2(float x, float y) {
    ull r;
    asm("mov.b64 %0, {%1, %2};" : "=l"(r) : "f"(x), "f"(y));
    return r;
}
__device__ __forceinline__ float2 unpack2(ull v) {
    float2 r;
    asm("mov.b64 {%0, %1}, %2;" : "=f"(r.x), "=f"(r.y) : "l"(v));
    return r;
}

// ---------------- generic fill ----------------
__global__ void fill_k(unsigned* __restrict__ ptr, unsigned v, size_t n) {
    size_t i = ((size_t)blockIdx.x * blockDim.x + threadIdx.x) * 4;
    if (i < n) {
        uint4 w; w.x = v; w.y = v; w.z = v; w.w = v;
        *(uint4*)(ptr + i) = w;
    }
}

// ---------------- flagged SGEMM (R2 mainloop; SCAT is compile-time) ----------
// C[m][n] = act( sum_k actIn(A[m][k]) W[k][n] + bias + bias2 + add )
// runtime flags: 1=relu_in, 2=relu_out, 4=store, 8=column-max epilogue
// template SCAT: 0=none, 16=scatter-max into g_bins, 32=scatter-add into g_bins
template<int SCAT>
__global__ void __launch_bounds__(256, 2)
gemm_k(const float* __restrict__ A, int lda, int K,
       const float* __restrict__ W, int ldw,
       const float* __restrict__ bias,
       const float* __restrict__ addsrc, int ldadd,
       const float* __restrict__ bias2,
       float* __restrict__ C, int ldc, int ccol,
       unsigned* __restrict__ colmax,
       int flags, int vec)
{
    __shared__ __align__(16) float As[16][128];   // k-major
    __shared__ __align__(16) float Ws[16][128];   // k-major (n contiguous)
    __shared__ unsigned smax[128];
    __shared__ int sidx[3][128];                  // smem only; no reg cost when unused

    const int t  = threadIdx.x;
    const int tx = t & 15, ty = t >> 4;
    const int m0 = blockIdx.x * 128;
    const int nbase = blockIdx.y * 128;

    // A staging: chunk c in [0,512): row=c>>2 (0..127), kseg=c&3 (4 floats along k)
    const int ca0   = t * 2,        ca1   = t * 2 + 1;
    const int arow0 = ca0 >> 2,     arow1 = ca1 >> 2;
    const int aks0  = ca0 & 3,      aks1  = ca1 & 3;
    // W staging: chunk c in [0,512): kl=c>>5 (0..15), n=(c&31)*4
    const int wkl0  = ca0 >> 5,     wkl1  = ca1 >> 5;
    const int wn0   = (ca0 & 31)*4, wn1   = (ca1 & 31)*4;

    float4 ar0, ar1, wr0, wr1;

    auto loadA = [&](int k0) {
        if (vec) {
            ar0 = *(const float4*)(A + (size_t)(m0 + arow0) * lda + k0 + aks0 * 4);
            ar1 = *(const float4*)(A + (size_t)(m0 + arow1) * lda + k0 + aks1 * 4);
        } else {
            float v[8];
#pragma unroll
            for (int q = 0; q < 4; q++) {
                int k = k0 + aks0 * 4 + q;
                v[q] = (k < K) ? A[(size_t)(m0 + arow0) * lda + k] : 0.f;
            }
#pragma unroll
            for (int q = 0; q < 4; q++) {
                int k = k0 + aks1 * 4 + q;
                v[4 + q] = (k < K) ? A[(size_t)(m0 + arow1) * lda + k] : 0.f;
            }
            ar0 = make_float4(v[0], v[1], v[2], v[3]);
            ar1 = make_float4(v[4], v[5], v[6], v[7]);
        }
    };
    auto loadW = [&](int k0) {
        if (vec) {
            wr0 = *(const float4*)(W + (size_t)(k0 + wkl0) * ldw + nbase + wn0);
            wr1 = *(const float4*)(W + (size_t)(k0 + wkl1) * ldw + nbase + wn1);
        } else {
            float v[8];
#pragma unroll
            for (int q = 0; q < 4; q++) {
                int k = k0 + wkl0;
                v[q] = (k < K) ? W[(size_t)k * ldw + nbase + wn0 + q] : 0.f;
            }
#pragma unroll
            for (int q = 0; q < 4; q++) {
                int k = k0 + wkl1;
                v[4 + q] = (k < K) ? W[(size_t)k * ldw + nbase + wn1 + q] : 0.f;
            }
            wr0 = make_float4(v[0], v[1], v[2], v[3]);
            wr1 = make_float4(v[4], v[5], v[6], v[7]);
        }
    };
    auto stage = [&]() {
        const bool ri = (flags & 1);
        float a0[4] = {ar0.x, ar0.y, ar0.z, ar0.w};
        float a1[4] = {ar1.x, ar1.y, ar1.z, ar1.w};
#pragma unroll
        for (int q = 0; q < 4; q++) {
            As[aks0 * 4 + q][arow0] = ri ? fmaxf(a0[q], 0.f) : a0[q];
            As[aks1 * 4 + q][arow1] = ri ? fmaxf(a1[q], 0.f) : a1[q];
        }
        *(float4*)&Ws[wkl0][wn0] = wr0;
        *(float4*)&Ws[wkl1][wn1] = wr1;
    };

    ull acc[8][4];
#pragma unroll
    for (int i = 0; i < 8; i++)
#pragma unroll
        for (int j = 0; j < 4; j++) acc[i][j] = 0ull;

    loadA(0);
    loadW(0);

    for (int k0 = 0; k0 < K; k0 += 16) {
        stage();
        __syncthreads();
        if (k0 + 16 < K) { loadA(k0 + 16); loadW(k0 + 16); }

#pragma unroll
        for (int kk = 0; kk < 16; kk++) {
            float4 a0 = *(const float4*)&As[kk][ty * 8];
            float4 a1 = *(const float4*)&As[kk][ty * 8 + 4];
            float4 w0 = *(const float4*)&Ws[kk][tx * 8];
            float4 w1 = *(const float4*)&Ws[kk][tx * 8 + 4];
            ull b0 = pack2(w0.x, w0.y);
            ull b1 = pack2(w0.z, w0.w);
            ull b2 = pack2(w1.x, w1.y);
            ull b3 = pack2(w1.z, w1.w);
            float a[8] = {a0.x, a0.y, a0.z, a0.w, a1.x, a1.y, a1.z, a1.w};
#pragma unroll
            for (int i = 0; i < 8; i++) {
                ull aa = pack2(a[i], a[i]);
                fma2(acc[i][0], aa, b0);
                fma2(acc[i][1], aa, b1);
                fma2(acc[i][2], aa, b2);
                fma2(acc[i][3], aa, b3);
            }
        }
        __syncthreads();
    }

    const int batch = m0 >> 15;  // T = 32768

    if constexpr (SCAT != 0) {
        if (t < 128) {
            sidx[0][t] = g_idx[0 * M + m0 + t];
            sidx[1][t] = g_idx[1 * M + m0 + t];
            sidx[2][t] = g_idx[2 * M + m0 + t];
        }
        __syncthreads();
    }

    float mx[8];
#pragma unroll
    for (int j = 0; j < 8; j++) mx[j] = 0.f;

#pragma unroll
    for (int i = 0; i < 8; i++) {
        const int ml = ty * 8 + i;
        const int m  = m0 + ml;
#pragma unroll
        for (int j = 0; j < 4; j++) {
            float2 v2 = unpack2(acc[i][j]);
            float v[2] = {v2.x, v2.y};
#pragma unroll
            for (int h = 0; h < 2; h++) {
                const int nl = tx * 8 + 2 * j + h;
                float v1 = v[h];
                if (bias)   v1 += bias[nbase + nl];
                if (addsrc) v1 += addsrc[(size_t)m * ldadd + nl];
                if (bias2)  v1 += bias2[batch * 128 + nl];
                if (flags & 2) v1 = fmaxf(v1, 0.f);
                if (flags & 4) C[(size_t)m * ldc + ccol + nbase + nl] = v1;
                mx[2 * j + h] = fmaxf(mx[2 * j + h], v1);
                if constexpr (SCAT == 16) {
                    unsigned fv = ford(v1);
#pragma unroll
                    for (int l = 0; l < NP; l++) {
                        int idx = sidx[l][ml];
                        atomicMax(&g_bins[(((size_t)((batch * NP + l) * R2 + idx)) << 7) + nl], fv);
                    }
                } else if constexpr (SCAT == 32) {
                    float* binsf = (float*)g_bins;
#pragma unroll
                    for (int l = 0; l < NP; l++) {
                        int idx = sidx[l][ml];
                        atomicAdd(&binsf[(((size_t)((batch * NP + l) * R2 + idx)) << 7) + nl], v1);
                    }
                }
            }
        }
    }

    if (flags & 8) {
        if (t < 128) smax[t] = 0u;
        __syncthreads();
#pragma unroll
        for (int j = 0; j < 8; j++)
            atomicMax(&smax[tx * 8 + j], __float_as_uint(mx[j]));
        __syncthreads();
        if (t < 128) atomicMax(&colmax[batch * 128 + t], smax[t]);
    }
}

// ---------------- tiny B=8 head: h3, pln_out, change_basis, net_pl ----------------
__global__ void __launch_bounds__(1024)
small_k(const float* __restrict__ h3w, const float* __restrict__ h3b,
        const float* __restrict__ outw, const float* __restrict__ outb,
        const float* __restrict__ hdw,  const float* __restrict__ hdb)
{
    __shared__ float hm[B * 128];
    __shared__ float h3s[B * 128];
    __shared__ float raw[B * 9];

    const int t = threadIdx.x;
    hm[t] = __uint_as_float(g_hmax[t]);
    __syncthreads();

    {   // h3 = relu(hmax @ h3_w + b)
        int b = t >> 7, j = t & 127;
        float acc = h3b[j];
        for (int k = 0; k < 128; k++)
            acc = fmaf(hm[b * 128 + k], h3w[k * 128 + j], acc);
        h3s[t] = fmaxf(acc, 0.f);
    }
    __syncthreads();

    if (t < 72) {   // net_pl_raw = h3 @ pln_out_w + b  (B x 9)
        int b = t / 9, o = t % 9;
        float acc = outb[o];
        for (int k = 0; k < 128; k++)
            acc = fmaf(h3s[b * 128 + k], outw[k * 9 + o], acc);
        raw[t] = acc;
    }
    __syncthreads();

    {   // net_pl = relu(raw) @ plane_hdim_w + b
        int b = t >> 7, j = t & 127;
        float acc = hdb[j];
        for (int o = 0; o < 9; o++)
            acc = fmaf(fmaxf(raw[b * 9 + o], 0.f), hdw[o * 128 + j], acc);
        g_netpl[t] = acc;
    }

    if (t < 24) {   // change_basis per (batch, plane)
        int b = t / 3, l = t % 3;
        float q0 = raw[b * 9 + 3 * l + 0];
        float q1 = raw[b * 9 + 3 * l + 1];
        float q2 = raw[b * 9 + 3 * l + 2];
        float nr = sqrtf(q0 * q0 + q1 * q1 + q2 * q2);
        float n0 = q0 / nr + 1e-6f;
        float n1 = q1 / nr + 1e-6f;
        float n2 = q2 / nr + 1e-6f;
        float v0 = -n1, v1 = n0, v2 = 0.f;
        float S[9] = { 0.f, -v2,  v1,
                       v2,  0.f, -v0,
                      -v1,  v0,  0.f };
        float S2[9];
        for (int i = 0; i < 3; i++)
            for (int j = 0; j < 3; j++) {
                float s = 0.f;
                for (int k = 0; k < 3; k++) s += S[i * 3 + k] * S[k * 3 + j];
                S2[i * 3 + j] = s;
            }
        float coef = (1.f - n2) / (v0 * v0 + v1 * v1 + v2 * v2);
        float R[9];
        for (int i = 0; i < 3; i++)
            for (int j = 0; j < 3; j++)
                R[i * 3 + j] = (i == j ? 1.f : 0.f) + S[i * 3 + j] + S2[i * 3 + j] * coef;
        float c00 =  (R[4] * R[8] - R[5] * R[7]);
        float c01 = -(R[3] * R[8] - R[5] * R[6]);
        float c02 =  (R[3] * R[7] - R[4] * R[6]);
        float det = R[0] * c00 + R[1] * c01 + R[2] * c02;
        float inv[9];
        inv[0] =  c00 / det;
        inv[1] = -(R[1] * R[8] - R[2] * R[7]) / det;
        inv[2] =  (R[1] * R[5] - R[2] * R[4]) / det;
        inv[3] =  c01 / det;
        inv[4] =  (R[0] * R[8] - R[2] * R[6]) / det;
        inv[5] = -(R[0] * R[5] - R[2] * R[3]) / det;
        inv[6] =  c02 / det;
        inv[7] = -(R[0] * R[7] - R[1] * R[6]) / det;
        inv[8] =  (R[0] * R[4] - R[1] * R[3]) / det;
        float bx0 = fabsf(R[0]), bx1 = fabsf(R[3]), bx2 = fabsf(R[6]);
        float by0 = fabsf(R[1]), by1 = fabsf(R[4]), by2 = fabsf(R[7]);
        float sx = bx0 + bx1 + bx2, sx2 = bx0 * bx0 + bx1 * bx1 + bx2 * bx2;
        float sy = by0 + by1 + by2, sy2 = by0 * by0 + by1 * by1 + by2 * by2;
        float nm = fmaxf(sx / sqrtf(sx2), sy / sqrtf(sy2));
        float* o = &g_Cmat[t * 12];
        for (int k = 0; k < 9; k++) o[k] = inv[k];
        o[9] = nm; o[10] = nm; o[11] = nm;
    }
}

// ---------------- per-point plane indices + bin counts ----------------
__global__ void __launch_bounds__(256)
idx_k(const float* __restrict__ p)
{
    __shared__ float Csh[B * NP * 12];
    const int t = threadIdx.x;
    for (int i = t; i < B * NP * 12; i += 256) Csh[i] = g_Cmat[i];
    __syncthreads();

    const int m = blockIdx.x * 256 + t;
    const float px = p[(size_t)m * 3 + 0];
    const float py = p[(size_t)m * 3 + 1];
    const float pz = p[(size_t)m * 3 + 2];
    const int b = m >> 15;
    const float denom = 1.0f + 0.1f + 0.001f;
    float* cntf = (float*)g_cnt;
#pragma unroll
    for (int l = 0; l < NP; l++) {
        const float* C = &Csh[(b * NP + l) * 12];
        float norm = C[9];
        float q0 = (C[0] * px + C[1] * py + C[2] * pz) / norm;
        float q1 = (C[3] * px + C[4] * py + C[5] * pz) / norm;
        float x = q0 / denom + 0.5f;
        float y = q1 / denom + 0.5f;
        x = fminf(fmaxf(x, 0.f), 1.f - 1e-5f);
        y = fminf(fmaxf(y, 0.f), 1.f - 1e-5f);
        int i = min(max((int)(x * (float)RESO), 0), RESO - 1);
        int j = min(max((int)(y * (float)RESO), 0), RESO - 1);
        int idx = i + RESO * j;
        g_idx[l * M + m] = idx;
        atomicAdd(&cntf[(b * NP + l) * R2 + idx], 1.f);
    }
}

// ---------------- gather pooled sums into x256 upper half ----------------
__global__ void __launch_bounds__(256)
gather_k()
{
    const int m = blockIdx.x * 2 + (threadIdx.x >> 7);
    const int c = threadIdx.x & 127;
    const int b = m >> 15;
    float s = 0.f;
#pragma unroll
    for (int l = 0; l < NP; l++) {
        int idx = g_idx[l * M + m];
        s += iford(g_bins[(((size_t)((b * NP + l) * R2 + idx)) << 7) + c]);
    }
    g_x256[(size_t)m * 256 + 128 + c] = s;
}

// ---------------- finalize: mean grids, transposed writeback ----------------
__global__ void __launch_bounds__(256)
finalize_k(float* __restrict__ out)
{
    __shared__ float tile[32][129];
    const int blk = blockIdx.x;
    const int pl = blk >> 7;
    const int r0 = (blk & 127) << 5;
    const int t = threadIdx.x;
    const float* binsf = (const float*)g_bins;
#pragma unroll
    for (int i = 0; i < 16; i++) {
        int idx = t + i * 256;
        int rl = idx >> 7, c = idx & 127;
        int r2 = r0 + rl;
        float cnt = __uint_as_float(g_cnt[pl * R2 + r2]);
        tile[rl][c] = binsf[((size_t)pl * R2 + r2) * 128 + c] / fmaxf(cnt, 1.f);
    }
    __syncthreads();
#pragma unroll
    for (int i = 0; i < 16; i++) {
        int idx = t + i * 256;
        int c = idx >> 5, rl = idx & 31;
        out[((size_t)pl * 128 + c) * R2 + r0 + rl] = tile[rl][c];
    }
}

__global__ void copy_cmat_k(float* __restrict__ out)
{
    int t = threadIdx.x;
    if (t < B * NP * 12) out[t] = g_Cmat[t];
}

// ---------------- driver ----------------
extern "C" void kernel_launch(void* const* d_in, const int* in_sizes, int n_in,
                              void* d_out, int out_size)
{
    const float* p        = (const float*)d_in[0];
    const float* pln_in_w = (const float*)d_in[1];
    const float* pln_in_b = (const float*)d_in[2];
    const float* h1w      = (const float*)d_in[3];
    const float* h1b      = (const float*)d_in[4];
    const float* h2w      = (const float*)d_in[5];
    const float* h2b      = (const float*)d_in[6];
    const float* h3w      = (const float*)d_in[7];
    const float* h3b      = (const float*)d_in[8];
    const float* outw     = (const float*)d_in[9];
    const float* outb     = (const float*)d_in[10];
    const float* hdw      = (const float*)d_in[11];
    const float* hdb      = (const float*)d_in[12];
    const float* fcposw   = (const float*)d_in[13];
    const float* fcposb   = (const float*)d_in[14];
    const float* fc0w     = (const float*)d_in[15];
    const float* fc0b     = (const float*)d_in[16];
    const float* fc1w     = (const float*)d_in[17];
    const float* fc1b     = (const float*)d_in[18];
    const float* scw      = (const float*)d_in[19];
    const float* fccw     = (const float*)d_in[20];
    const float* fccb     = (const float*)d_in[21];
    float* out = (float*)d_out;

    float *tmp = nullptr, *dx = nullptr, *x256 = nullptr, *netpl = nullptr;
    unsigned *hmax = nullptr, *bins = nullptr, *cnt = nullptr;
    cudaGetSymbolAddress((void**)&tmp,   g_tmp);
    cudaGetSymbolAddress((void**)&dx,    g_dx);
    cudaGetSymbolAddress((void**)&x256,  g_x256);
    cudaGetSymbolAddress((void**)&netpl, g_netpl);
    cudaGetSymbolAddress((void**)&hmax,  g_hmax);
    cudaGetSymbolAddress((void**)&bins,  g_bins);
    cudaGetSymbolAddress((void**)&cnt,   g_cnt);

    unsigned NEG;
    { float f = -1e30f; unsigned u; memcpy(&u, &f, 4); NEG = ~u; }

    const dim3 gB(M / 128, 1);
    const int GEMM_T = 256;

    // ---- counts buffer (accumulated once by idx_k) ----
    fill_k<<<(int)(NCNT / 4 / 256), 256>>>(cnt, 0u, NCNT);

    // ---- stage 1: point MLP + per-batch column max ----
    gemm_k<0><<<gB, GEMM_T>>>(p, 3, 3, pln_in_w, 128, pln_in_b,
                              nullptr, 0, nullptr, tmp, 128, 0, nullptr, 2 | 4, 0);
    gemm_k<0><<<gB, GEMM_T>>>(tmp, 128, 128, h1w, 128, h1b,
                              nullptr, 0, nullptr, dx, 128, 0, nullptr, 2 | 4, 1);
    fill_k<<<1, 256>>>(hmax, 0u, (size_t)B * 128);
    gemm_k<0><<<gB, GEMM_T>>>(dx, 128, 128, h2w, 128, h2b,
                              nullptr, 0, nullptr, nullptr, 0, 0, hmax, 2 | 8, 1);

    // ---- tiny head + plane indices (+counts) ----
    small_k<<<1, 1024>>>(h3w, h3b, outw, outb, hdw, hdb);
    idx_k<<<M / 256, 256>>>(p);

    // ---- fc_pos: p -> 256-wide net in x256 ----
    gemm_k<0><<<dim3(M / 128, 2), GEMM_T>>>(p, 3, 3, fcposw, 256, fcposb,
                                            nullptr, 0, nullptr, x256, 256, 0, nullptr, 4, 0);

    // ---- residual blocks; scatter-max fused into sc epilogue for j<4 ----
    for (int j = 0; j < 5; j++) {
        // n0 = relu(x) @ fc0 + b0  -> tmp
        gemm_k<0><<<gB, GEMM_T>>>(x256, 256, 256, fc0w + (size_t)j * 256 * 128, 128,
                                  fc0b + j * 128, nullptr, 0, nullptr,
                                  tmp, 128, 0, nullptr, 1 | 4, 1);
        // dx = relu(n0) @ fc1 + b1 -> dx
        gemm_k<0><<<gB, GEMM_T>>>(tmp, 128, 128, fc1w + (size_t)j * 128 * 128, 128,
                                  fc1b + j * 128, nullptr, 0, nullptr,
                                  dx, 128, 0, nullptr, 1 | 4, 1);
        // net = x @ sc + dx -> x256 lower half (+ fused scatter-max for j<4)
        if (j < 4) {
            fill_k<<<(int)(NBINS / 4 / 256), 256>>>(bins, NEG, NBINS);
            gemm_k<16><<<gB, GEMM_T>>>(x256, 256, 256, scw + (size_t)j * 256 * 128, 128,
                                       nullptr, dx, 128, nullptr,
                                       x256, 256, 0, nullptr, 4, 1);
            gather_k<<<M / 2, 256>>>();
        } else {
            gemm_k<0><<<gB, GEMM_T>>>(x256, 256, 256, scw + (size_t)j * 256 * 128, 128,
                                      nullptr, dx, 128, nullptr,
                                      x256, 256, 0, nullptr, 4, 1);
        }
    }

    // ---- c = net@fc_c + b + net_pl ; fused scatter-add (c never stored) ----
    fill_k<<<(int)(NBINS / 4 / 256), 256>>>(bins, 0u, NBINS);
    gemm_k<32><<<gB, GEMM_T>>>(x256, 256, 128, fccw, 128, fccb,
                               nullptr, 0, netpl, nullptr, 0, 0, nullptr, 32 /*unused runtime*/ & 0 | 0, 1);

    // ---- plane features + C_mat tail ----
    finalize_k<<<B * NP * (R2 / 32), 256>>>(out);
    copy_cmat_k<<<1, 288>>>(out + (size_t)out_size - B * NP * 12);
}

// round 11
// speedup vs baseline: 1.0021x; 1.0021x over previous
#include <cuda_runtime.h>
#include <cstdint>
#include <cstddef>
#include <string.h>

// ---------------- problem constants ----------------
constexpr int B    = 8;
constexpr int T    = 32768;
constexpr int M    = B * T;          // 262144 points
constexpr int NP   = 3;
constexpr int RESO = 64;
constexpr int R2   = RESO * RESO;    // 4096
constexpr size_t NBINS = (size_t)B * NP * R2 * 128;   // 12,582,912
constexpr size_t NCNT  = (size_t)B * NP * R2;         // 98,304

typedef unsigned long long ull;

// ---------------- scratch (__device__ globals; no allocation) ----------------
__device__ float    g_x256[(size_t)M * 256];   // [net | pooled] concat buffer
__device__ float    g_tmp [(size_t)M * 128];   // n0 temp
__device__ float    g_dx  [(size_t)M * 128];   // dx temp
__device__ int      g_idx [3 * M];             // plane bin indices
__device__ unsigned g_hmax[B * 128];           // column max (float bits, >=0)
__device__ float    g_netpl[B * 128];
__device__ float    g_Cmat[B * NP * 12];       // (4,3) per plane
__device__ unsigned g_bins[NBINS];             // scatter-max (encoded) / scatter-add (float bits)
__device__ unsigned g_cnt [NCNT];              // float bits

// ---------------- helpers ----------------
__device__ __forceinline__ unsigned ford(float f) {
    unsigned u = __float_as_uint(f);
    return (f >= 0.f) ? (u | 0x80000000u) : ~u;
}
__device__ __forceinline__ float iford(unsigned u) {
    return (u & 0x80000000u) ? __uint_as_float(u & 0x7FFFFFFFu) : __uint_as_float(~u);
}

__device__ __forceinline__ void fma2(ull& acc, ull a, ull b) {
    asm("fma.rn.f32x2 %0, %1, %2, %0;" : "+l"(acc) : "l"(a), "l"(b));
}
__device__ __forceinline__ ull pack2(float x, float y) {
    ull r;
    asm("mov.b64 %0, {%1, %2};" : "=l"(r) : "f"(x), "f"(y));
    return r;
}
__device__ __forceinline__ float2 unpack2(ull v) {
    float2 r;
    asm("mov.b64 {%0, %1}, %2;" : "=f"(r.x), "=f"(r.y) : "l"(v));
    return r;
}

// ---------------- generic fill ----------------
__global__ void fill_k(unsigned* __restrict__ ptr, unsigned v, size_t n) {
    size_t i = ((size_t)blockIdx.x * blockDim.x + threadIdx.x) * 4;
    if (i < n) {
        uint4 w; w.x = v; w.y = v; w.z = v; w.w = v;
        *(uint4*)(ptr + i) = w;
    }
}

// ---------------- flagged SGEMM (R2 mainloop; SCAT is compile-time) ----------
// C[m][n] = act( sum_k actIn(A[m][k]) W[k][n] + bias + bias2 + add )
// runtime flags: 1=relu_in, 2=relu_out, 4=store, 8=column-max epilogue
// template SCAT: 0=none, 16=scatter-max into g_bins, 32=scatter-add into g_bins
template<int SCAT>
__global__ void __launch_bounds__(256, 2)
gemm_k(const float* __restrict__ A, int lda, int K,
       const float* __restrict__ W, int ldw,
       const float* __restrict__ bias,
       const float* __restrict__ addsrc, int ldadd,
       const float* __restrict__ bias2,
       float* __restrict__ C, int ldc, int ccol,
       unsigned* __restrict__ colmax,
       int flags, int vec)
{
    __shared__ __align__(16) float As[16][128];   // k-major
    __shared__ __align__(16) float Ws[16][128];   // k-major (n contiguous)
    __shared__ unsigned smax[128];
    __shared__ int sidx[3][128];                  // smem only; no reg cost when unused

    const int t  = threadIdx.x;
    const int tx = t & 15, ty = t >> 4;
    const int m0 = blockIdx.x * 128;
    const int nbase = blockIdx.y * 128;

    // A staging: chunk c in [0,512): row=c>>2 (0..127), kseg=c&3 (4 floats along k)
    const int ca0   = t * 2,        ca1   = t * 2 + 1;
    const int arow0 = ca0 >> 2,     arow1 = ca1 >> 2;
    const int aks0  = ca0 & 3,      aks1  = ca1 & 3;
    // W staging: chunk c in [0,512): kl=c>>5 (0..15), n=(c&31)*4
    const int wkl0  = ca0 >> 5,     wkl1  = ca1 >> 5;
    const int wn0   = (ca0 & 31)*4, wn1   = (ca1 & 31)*4;

    float4 ar0, ar1, wr0, wr1;

    auto loadA = [&](int k0) {
        if (vec) {
            ar0 = *(const float4*)(A + (size_t)(m0 + arow0) * lda + k0 + aks0 * 4);
            ar1 = *(const float4*)(A + (size_t)(m0 + arow1) * lda + k0 + aks1 * 4);
        } else {
            float v[8];
#pragma unroll
            for (int q = 0; q < 4; q++) {
                int k = k0 + aks0 * 4 + q;
                v[q] = (k < K) ? A[(size_t)(m0 + arow0) * lda + k] : 0.f;
            }
#pragma unroll
            for (int q = 0; q < 4; q++) {
                int k = k0 + aks1 * 4 + q;
                v[4 + q] = (k < K) ? A[(size_t)(m0 + arow1) * lda + k] : 0.f;
            }
            ar0 = make_float4(v[0], v[1], v[2], v[3]);
            ar1 = make_float4(v[4], v[5], v[6], v[7]);
        }
    };
    auto loadW = [&](int k0) {
        if (vec) {
            wr0 = *(const float4*)(W + (size_t)(k0 + wkl0) * ldw + nbase + wn0);
            wr1 = *(const float4*)(W + (size_t)(k0 + wkl1) * ldw + nbase + wn1);
        } else {
            float v[8];
#pragma unroll
            for (int q = 0; q < 4; q++) {
                int k = k0 + wkl0;
                v[q] = (k < K) ? W[(size_t)k * ldw + nbase + wn0 + q] : 0.f;
            }
#pragma unroll
            for (int q = 0; q < 4; q++) {
                int k = k0 + wkl1;
                v[4 + q] = (k < K) ? W[(size_t)k * ldw + nbase + wn1 + q] : 0.f;
            }
            wr0 = make_float4(v[0], v[1], v[2], v[3]);
            wr1 = make_float4(v[4], v[5], v[6], v[7]);
        }
    };
    auto stage = [&]() {
        const bool ri = (flags & 1);
        float a0[4] = {ar0.x, ar0.y, ar0.z, ar0.w};
        float a1[4] = {ar1.x, ar1.y, ar1.z, ar1.w};
#pragma unroll
        for (int q = 0; q < 4; q++) {
            As[aks0 * 4 + q][arow0] = ri ? fmaxf(a0[q], 0.f) : a0[q];
            As[aks1 * 4 + q][arow1] = ri ? fmaxf(a1[q], 0.f) : a1[q];
        }
        *(float4*)&Ws[wkl0][wn0] = wr0;
        *(float4*)&Ws[wkl1][wn1] = wr1;
    };

    ull acc[8][4];
#pragma unroll
    for (int i = 0; i < 8; i++)
#pragma unroll
        for (int j = 0; j < 4; j++) acc[i][j] = 0ull;

    loadA(0);
    loadW(0);

    for (int k0 = 0; k0 < K; k0 += 16) {
        stage();
        __syncthreads();
        if (k0 + 16 < K) { loadA(k0 + 16); loadW(k0 + 16); }

#pragma unroll
        for (int kk = 0; kk < 16; kk++) {
            float4 a0 = *(const float4*)&As[kk][ty * 8];
            float4 a1 = *(const float4*)&As[kk][ty * 8 + 4];
            float4 w0 = *(const float4*)&Ws[kk][tx * 8];
            float4 w1 = *(const float4*)&Ws[kk][tx * 8 + 4];
            ull b0 = pack2(w0.x, w0.y);
            ull b1 = pack2(w0.z, w0.w);
            ull b2 = pack2(w1.x, w1.y);
            ull b3 = pack2(w1.z, w1.w);
            float a[8] = {a0.x, a0.y, a0.z, a0.w, a1.x, a1.y, a1.z, a1.w};
#pragma unroll
            for (int i = 0; i < 8; i++) {
                ull aa = pack2(a[i], a[i]);
                fma2(acc[i][0], aa, b0);
                fma2(acc[i][1], aa, b1);
                fma2(acc[i][2], aa, b2);
                fma2(acc[i][3], aa, b3);
            }
        }
        __syncthreads();
    }

    const int batch = m0 >> 15;  // T = 32768

    if constexpr (SCAT != 0) {
        if (t < 128) {
            sidx[0][t] = g_idx[0 * M + m0 + t];
            sidx[1][t] = g_idx[1 * M + m0 + t];
            sidx[2][t] = g_idx[2 * M + m0 + t];
        }
        __syncthreads();
    }

    float mx[8];
#pragma unroll
    for (int j = 0; j < 8; j++) mx[j] = 0.f;

#pragma unroll
    for (int i = 0; i < 8; i++) {
        const int ml = ty * 8 + i;
        const int m  = m0 + ml;
#pragma unroll
        for (int j = 0; j < 4; j++) {
            float2 v2 = unpack2(acc[i][j]);
            float v[2] = {v2.x, v2.y};
#pragma unroll
            for (int h = 0; h < 2; h++) {
                const int nl = tx * 8 + 2 * j + h;
                float v1 = v[h];
                if (bias)   v1 += bias[nbase + nl];
                if (addsrc) v1 += addsrc[(size_t)m * ldadd + nl];
                if (bias2)  v1 += bias2[batch * 128 + nl];
                if (flags & 2) v1 = fmaxf(v1, 0.f);
                if (flags & 4) C[(size_t)m * ldc + ccol + nbase + nl] = v1;
                mx[2 * j + h] = fmaxf(mx[2 * j + h], v1);
                if constexpr (SCAT == 16) {
                    unsigned fv = ford(v1);
#pragma unroll
                    for (int l = 0; l < NP; l++) {
                        int idx = sidx[l][ml];
                        atomicMax(&g_bins[(((size_t)((batch * NP + l) * R2 + idx)) << 7) + nl], fv);
                    }
                } else if constexpr (SCAT == 32) {
                    float* binsf = (float*)g_bins;
#pragma unroll
                    for (int l = 0; l < NP; l++) {
                        int idx = sidx[l][ml];
                        atomicAdd(&binsf[(((size_t)((batch * NP + l) * R2 + idx)) << 7) + nl], v1);
                    }
                }
            }
        }
    }

    if (flags & 8) {
        if (t < 128) smax[t] = 0u;
        __syncthreads();
#pragma unroll
        for (int j = 0; j < 8; j++)
            atomicMax(&smax[tx * 8 + j], __float_as_uint(mx[j]));
        __syncthreads();
        if (t < 128) atomicMax(&colmax[batch * 128 + t], smax[t]);
    }
}

// ---------------- tiny B=8 head: h3, pln_out, change_basis, net_pl ----------------
__global__ void __launch_bounds__(1024)
small_k(const float* __restrict__ h3w, const float* __restrict__ h3b,
        const float* __restrict__ outw, const float* __restrict__ outb,
        const float* __restrict__ hdw,  const float* __restrict__ hdb)
{
    __shared__ float hm[B * 128];
    __shared__ float h3s[B * 128];
    __shared__ float raw[B * 9];

    const int t = threadIdx.x;
    hm[t] = __uint_as_float(g_hmax[t]);
    __syncthreads();

    {   // h3 = relu(hmax @ h3_w + b)
        int b = t >> 7, j = t & 127;
        float acc = h3b[j];
        for (int k = 0; k < 128; k++)
            acc = fmaf(hm[b * 128 + k], h3w[k * 128 + j], acc);
        h3s[t] = fmaxf(acc, 0.f);
    }
    __syncthreads();

    if (t < 72) {   // net_pl_raw = h3 @ pln_out_w + b  (B x 9)
        int b = t / 9, o = t % 9;
        float acc = outb[o];
        for (int k = 0; k < 128; k++)
            acc = fmaf(h3s[b * 128 + k], outw[k * 9 + o], acc);
        raw[t] = acc;
    }
    __syncthreads();

    {   // net_pl = relu(raw) @ plane_hdim_w + b
        int b = t >> 7, j = t & 127;
        float acc = hdb[j];
        for (int o = 0; o < 9; o++)
            acc = fmaf(fmaxf(raw[b * 9 + o], 0.f), hdw[o * 128 + j], acc);
        g_netpl[t] = acc;
    }

    if (t < 24) {   // change_basis per (batch, plane)
        int b = t / 3, l = t % 3;
        float q0 = raw[b * 9 + 3 * l + 0];
        float q1 = raw[b * 9 + 3 * l + 1];
        float q2 = raw[b * 9 + 3 * l + 2];
        float nr = sqrtf(q0 * q0 + q1 * q1 + q2 * q2);
        float n0 = q0 / nr + 1e-6f;
        float n1 = q1 / nr + 1e-6f;
        float n2 = q2 / nr + 1e-6f;
        float v0 = -n1, v1 = n0, v2 = 0.f;
        float S[9] = { 0.f, -v2,  v1,
                       v2,  0.f, -v0,
                      -v1,  v0,  0.f };
        float S2[9];
        for (int i = 0; i < 3; i++)
            for (int j = 0; j < 3; j++) {
                float s = 0.f;
                for (int k = 0; k < 3; k++) s += S[i * 3 + k] * S[k * 3 + j];
                S2[i * 3 + j] = s;
            }
        float coef = (1.f - n2) / (v0 * v0 + v1 * v1 + v2 * v2);
        float R[9];
        for (int i = 0; i < 3; i++)
            for (int j = 0; j < 3; j++)
                R[i * 3 + j] = (i == j ? 1.f : 0.f) + S[i * 3 + j] + S2[i * 3 + j] * coef;
        float c00 =  (R[4] * R[8] - R[5] * R[7]);
        float c01 = -(R[3] * R[8] - R[5] * R[6]);
        float c02 =  (R[3] * R[7] - R[4] * R[6]);
        float det = R[0] * c00 + R[1] * c01 + R[2] * c02;
        float inv[9];
        inv[0] =  c00 / det;
        inv[1] = -(R[1] * R[8] - R[2] * R[7]) / det;
        inv[2] =  (R[1] * R[5] - R[2] * R[4]) / det;
        inv[3] =  c01 / det;
        inv[4] =  (R[0] * R[8] - R[2] * R[6]) / det;
        inv[5] = -(R[0] * R[5] - R[2] * R[3]) / det;
        inv[6] =  c02 / det;
        inv[7] = -(R[0] * R[7] - R[1] * R[6]) / det;
        inv[8] =  (R[0] * R[4] - R[1] * R[3]) / det;
        float bx0 = fabsf(R[0]), bx1 = fabsf(R[3]), bx2 = fabsf(R[6]);
        float by0 = fabsf(R[1]), by1 = fabsf(R[4]), by2 = fabsf(R[7]);
        float sx = bx0 + bx1 + bx2, sx2 = bx0 * bx0 + bx1 * bx1 + bx2 * bx2;
        float sy = by0 + by1 + by2, sy2 = by0 * by0 + by1 * by1 + by2 * by2;
        float nm = fmaxf(sx / sqrtf(sx2), sy / sqrtf(sy2));
        float* o = &g_Cmat[t * 12];
        for (int k = 0; k < 9; k++) o[k] = inv[k];
        o[9] = nm; o[10] = nm; o[11] = nm;
    }
}

// ---------------- per-point plane indices + bin counts ----------------
__global__ void __launch_bounds__(256)
idx_k(const float* __restrict__ p)
{
    __shared__ float Csh[B * NP * 12];
    const int t = threadIdx.x;
    for (int i = t; i < B * NP * 12; i += 256) Csh[i] = g_Cmat[i];
    __syncthreads();

    const int m = blockIdx.x * 256 + t;
    const float px = p[(size_t)m * 3 + 0];
    const float py = p[(size_t)m * 3 + 1];
    const float pz = p[(size_t)m * 3 + 2];
    const int b = m >> 15;
    const float denom = 1.0f + 0.1f + 0.001f;
    float* cntf = (float*)g_cnt;
#pragma unroll
    for (int l = 0; l < NP; l++) {
        const float* C = &Csh[(b * NP + l) * 12];
        float norm = C[9];
        float q0 = (C[0] * px + C[1] * py + C[2] * pz) / norm;
        float q1 = (C[3] * px + C[4] * py + C[5] * pz) / norm;
        float x = q0 / denom + 0.5f;
        float y = q1 / denom + 0.5f;
        x = fminf(fmaxf(x, 0.f), 1.f - 1e-5f);
        y = fminf(fmaxf(y, 0.f), 1.f - 1e-5f);
        int i = min(max((int)(x * (float)RESO), 0), RESO - 1);
        int j = min(max((int)(y * (float)RESO), 0), RESO - 1);
        int idx = i + RESO * j;
        g_idx[l * M + m] = idx;
        atomicAdd(&cntf[(b * NP + l) * R2 + idx], 1.f);
    }
}

// ---------------- gather pooled sums into x256 upper half ----------------
__global__ void __launch_bounds__(256)
gather_k()
{
    const int m = blockIdx.x * 2 + (threadIdx.x >> 7);
    const int c = threadIdx.x & 127;
    const int b = m >> 15;
    float s = 0.f;
#pragma unroll
    for (int l = 0; l < NP; l++) {
        int idx = g_idx[l * M + m];
        s += iford(g_bins[(((size_t)((b * NP + l) * R2 + idx)) << 7) + c]);
    }
    g_x256[(size_t)m * 256 + 128 + c] = s;
}

// ---------------- finalize: mean grids, transposed writeback ----------------
__global__ void __launch_bounds__(256)
finalize_k(float* __restrict__ out)
{
    __shared__ float tile[32][129];
    const int blk = blockIdx.x;
    const int pl = blk >> 7;
    const int r0 = (blk & 127) << 5;
    const int t = threadIdx.x;
    const float* binsf = (const float*)g_bins;
#pragma unroll
    for (int i = 0; i < 16; i++) {
        int idx = t + i * 256;
        int rl = idx >> 7, c = idx & 127;
        int r2 = r0 + rl;
        float cnt = __uint_as_float(g_cnt[pl * R2 + r2]);
        tile[rl][c] = binsf[((size_t)pl * R2 + r2) * 128 + c] / fmaxf(cnt, 1.f);
    }
    __syncthreads();
#pragma unroll
    for (int i = 0; i < 16; i++) {
        int idx = t + i * 256;
        int c = idx >> 5, rl = idx & 31;
        out[((size_t)pl * 128 + c) * R2 + r0 + rl] = tile[rl][c];
    }
}

__global__ void copy_cmat_k(float* __restrict__ out)
{
    int t = threadIdx.x;
    if (t < B * NP * 12) out[t] = g_Cmat[t];
}

// ---------------- driver ----------------
extern "C" void kernel_launch(void* const* d_in, const int* in_sizes, int n_in,
                              void* d_out, int out_size)
{
    const float* p        = (const float*)d_in[0];
    const float* pln_in_w = (const float*)d_in[1];
    const float* pln_in_b = (const float*)d_in[2];
    const float* h1w      = (const float*)d_in[3];
    const float* h1b      = (const float*)d_in[4];
    const float* h2w      = (const float*)d_in[5];
    const float* h2b      = (const float*)d_in[6];
    const float* h3w      = (const float*)d_in[7];
    const float* h3b      = (const float*)d_in[8];
    const float* outw     = (const float*)d_in[9];
    const float* outb     = (const float*)d_in[10];
    const float* hdw      = (const float*)d_in[11];
    const float* hdb      = (const float*)d_in[12];
    const float* fcposw   = (const float*)d_in[13];
    const float* fcposb   = (const float*)d_in[14];
    const float* fc0w     = (const float*)d_in[15];
    const float* fc0b     = (const float*)d_in[16];
    const float* fc1w     = (const float*)d_in[17];
    const float* fc1b     = (const float*)d_in[18];
    const float* scw      = (const float*)d_in[19];
    const float* fccw     = (const float*)d_in[20];
    const float* fccb     = (const float*)d_in[21];
    float* out = (float*)d_out;

    float *tmp = nullptr, *dx = nullptr, *x256 = nullptr, *netpl = nullptr;
    unsigned *hmax = nullptr, *bins = nullptr, *cnt = nullptr;
    cudaGetSymbolAddress((void**)&tmp,   g_tmp);
    cudaGetSymbolAddress((void**)&dx,    g_dx);
    cudaGetSymbolAddress((void**)&x256,  g_x256);
    cudaGetSymbolAddress((void**)&netpl, g_netpl);
    cudaGetSymbolAddress((void**)&hmax,  g_hmax);
    cudaGetSymbolAddress((void**)&bins,  g_bins);
    cudaGetSymbolAddress((void**)&cnt,   g_cnt);

    unsigned NEG;
    { float f = -1e30f; unsigned u; memcpy(&u, &f, 4); NEG = ~u; }

    const dim3 gB(M / 128, 1);
    const int GEMM_T = 256;

    // ---- counts buffer (accumulated once by idx_k) ----
    fill_k<<<(int)(NCNT / 4 / 256), 256>>>(cnt, 0u, NCNT);

    // ---- stage 1: point MLP + per-batch column max ----
    gemm_k<0><<<gB, GEMM_T>>>(p, 3, 3, pln_in_w, 128, pln_in_b,
                              nullptr, 0, nullptr, tmp, 128, 0, nullptr, 2 | 4, 0);
    gemm_k<0><<<gB, GEMM_T>>>(tmp, 128, 128, h1w, 128, h1b,
                              nullptr, 0, nullptr, dx, 128, 0, nullptr, 2 | 4, 1);
    fill_k<<<1, 256>>>(hmax, 0u, (size_t)B * 128);
    gemm_k<0><<<gB, GEMM_T>>>(dx, 128, 128, h2w, 128, h2b,
                              nullptr, 0, nullptr, nullptr, 0, 0, hmax, 2 | 8, 1);

    // ---- tiny head + plane indices (+counts) ----
    small_k<<<1, 1024>>>(h3w, h3b, outw, outb, hdw, hdb);
    idx_k<<<M / 256, 256>>>(p);

    // ---- fc_pos: p -> 256-wide net in x256 ----
    gemm_k<0><<<dim3(M / 128, 2), GEMM_T>>>(p, 3, 3, fcposw, 256, fcposb,
                                            nullptr, 0, nullptr, x256, 256, 0, nullptr, 4, 0);

    // ---- residual blocks; scatter-max fused into sc epilogue for j<4 ----
    for (int j = 0; j < 5; j++) {
        // n0 = relu(x) @ fc0 + b0  -> tmp
        gemm_k<0><<<gB, GEMM_T>>>(x256, 256, 256, fc0w + (size_t)j * 256 * 128, 128,
                                  fc0b + j * 128, nullptr, 0, nullptr,
                                  tmp, 128, 0, nullptr, 1 | 4, 1);
        // dx = relu(n0) @ fc1 + b1 -> dx
        gemm_k<0><<<gB, GEMM_T>>>(tmp, 128, 128, fc1w + (size_t)j * 128 * 128, 128,
                                  fc1b + j * 128, nullptr, 0, nullptr,
                                  dx, 128, 0, nullptr, 1 | 4, 1);
        // net = x @ sc + dx -> x256 lower half (+ fused scatter-max for j<4)
        if (j < 4) {
            fill_k<<<(int)(NBINS / 4 / 256), 256>>>(bins, NEG, NBINS);
            gemm_k<16><<<gB, GEMM_T>>>(x256, 256, 256, scw + (size_t)j * 256 * 128, 128,
                                       nullptr, dx, 128, nullptr,
                                       x256, 256, 0, nullptr, 4, 1);
            gather_k<<<M / 2, 256>>>();
        } else {
            gemm_k<0><<<gB, GEMM_T>>>(x256, 256, 256, scw + (size_t)j * 256 * 128, 128,
                                      nullptr, dx, 128, nullptr,
                                      x256, 256, 0, nullptr, 4, 1);
        }
    }

    // ---- c = net@fc_c + b + net_pl ; fused scatter-add (c never stored) ----
    fill_k<<<(int)(NBINS / 4 / 256), 256>>>(bins, 0u, NBINS);
    gemm_k<32><<<gB, GEMM_T>>>(x256, 256, 128, fccw, 128, fccb,
                               nullptr, 0, netpl, nullptr, 0, 0, nullptr, 32 /*unused runtime*/ & 0 | 0, 1);

    // ---- plane features + C_mat tail ----
    finalize_k<<<B * NP * (R2 / 32), 256>>>(out);
    copy_cmat_k<<<1, 288>>>(out + (size_t)out_size - B * NP * 12);
}

// round 12
// speedup vs baseline: 1.1495x; 1.1471x over previous
#include <cuda_runtime.h>
#include <cstdint>
#include <cstddef>
#include <string.h>

// ---------------- problem constants ----------------
constexpr int B    = 8;
constexpr int T    = 32768;
constexpr int M    = B * T;          // 262144 points
constexpr int NP   = 3;
constexpr int RESO = 64;
constexpr int R2   = RESO * RESO;    // 4096
constexpr size_t NBINS = (size_t)B * NP * R2 * 128;   // 12,582,912
constexpr size_t NCNT  = (size_t)B * NP * R2;         // 98,304

typedef unsigned long long ull;

// ---------------- scratch (__device__ globals; no allocation) ----------------
__device__ float    g_x256[(size_t)M * 256];   // [net | pooled] concat buffer
__device__ float    g_tmp [(size_t)M * 128];   // generic 128-wide temp
__device__ float    g_dx  [(size_t)M * 128];   // dx temp
__device__ int      g_idx [3 * M];             // plane bin indices
__device__ unsigned g_hmax[B * 128];           // column max (float bits, >=0)
__device__ float    g_netpl[B * 128];
__device__ float    g_Cmat[B * NP * 12];       // (4,3) per plane
__device__ unsigned g_bins[NBINS];             // scatter-max (encoded) / scatter-add (float bits)
__device__ unsigned g_cnt [NCNT];              // float bits

// ---------------- helpers ----------------
__device__ __forceinline__ unsigned ford(float f) {
    unsigned u = __float_as_uint(f);
    return (f >= 0.f) ? (u | 0x80000000u) : ~u;
}
__device__ __forceinline__ float iford(unsigned u) {
    return (u & 0x80000000u) ? __uint_as_float(u & 0x7FFFFFFFu) : __uint_as_float(~u);
}

// packed fp32x2 FMA (FFMA2) — 2x fp32 throughput vs scalar FFMA (SASS_QUICKREF)
__device__ __forceinline__ void fma2(ull& acc, ull a, ull b) {
    asm("fma.rn.f32x2 %0, %1, %2, %0;" : "+l"(acc) : "l"(a), "l"(b));
}
__device__ __forceinline__ ull pack2(float x, float y) {
    ull r;
    asm("mov.b64 %0, {%1, %2};" : "=l"(r) : "f"(x), "f"(y));
    return r;
}
__device__ __forceinline__ float2 unpack2(ull v) {
    float2 r;
    asm("mov.b64 {%0, %1}, %2;" : "=f"(r.x), "=f"(r.y) : "l"(v));
    return r;
}

// ---------------- generic fill ----------------
__global__ void fill_k(unsigned* __restrict__ ptr, unsigned v, size_t n) {
    size_t i = ((size_t)blockIdx.x * blockDim.x + threadIdx.x) * 4;
    if (i < n) {
        uint4 w; w.x = v; w.y = v; w.z = v; w.w = v;
        *(uint4*)(ptr + i) = w;
    }
}

// ---------------- dedicated K=3 linear layer (memory-bound) ----------------
// C[m][n] = opt_relu( p[m]·W[:,n] + bias[n] ), W row-major (3 x N)
template<int N>
__global__ void __launch_bounds__(256)
linear3_k(const float* __restrict__ p, const float* __restrict__ W,
          const float* __restrict__ bias, float* __restrict__ C, int relu)
{
    const int t = threadIdx.x;
    int m, n;
    if (N == 128) { m = blockIdx.x * 2 + (t >> 7); n = t & 127; }
    else          { m = blockIdx.x;                n = t;       }
    float p0 = __ldg(&p[(size_t)m * 3 + 0]);
    float p1 = __ldg(&p[(size_t)m * 3 + 1]);
    float p2 = __ldg(&p[(size_t)m * 3 + 2]);
    float acc = fmaf(p0, __ldg(&W[n]),
                fmaf(p1, __ldg(&W[N + n]),
                     p2 * __ldg(&W[2 * N + n])));
    float v = acc + __ldg(&bias[n]);
    if (relu) v = fmaxf(v, 0.f);
    C[(size_t)m * N + n] = v;
}

// ---------------- flagged SGEMM with FFMA2 + register-staged prefetch ----------
// (byte-for-byte the R2 kernel that measured 7921.7us)
// flags: 1=relu_in, 2=relu_out, 4=store, 8=column-max epilogue (into colmax)
// vec:   1 when K%16==0 && lda%4==0 (vectorized float4 global loads)
__global__ void __launch_bounds__(256, 2)
gemm_k(const float* __restrict__ A, int lda, int K,
       const float* __restrict__ W, int ldw,
       const float* __restrict__ bias,
       const float* __restrict__ addsrc, int ldadd,
       const float* __restrict__ bias2,
       float* __restrict__ C, int ldc, int ccol,
       unsigned* __restrict__ colmax,
       int flags, int vec)
{
    __shared__ __align__(16) float As[16][128];   // k-major
    __shared__ __align__(16) float Ws[16][128];   // k-major (n contiguous)
    __shared__ unsigned smax[128];

    const int t  = threadIdx.x;
    const int tx = t & 15, ty = t >> 4;
    const int m0 = blockIdx.x * 128;
    const int nbase = blockIdx.y * 128;

    // A staging: chunk c in [0,512): row=c>>2 (0..127), kseg=c&3 (4 floats along k)
    const int ca0   = t * 2,        ca1   = t * 2 + 1;
    const int arow0 = ca0 >> 2,     arow1 = ca1 >> 2;
    const int aks0  = ca0 & 3,      aks1  = ca1 & 3;
    // W staging: chunk c in [0,512): kl=c>>5 (0..15), n=(c&31)*4
    const int wkl0  = ca0 >> 5,     wkl1  = ca1 >> 5;
    const int wn0   = (ca0 & 31)*4, wn1   = (ca1 & 31)*4;

    float4 ar0, ar1, wr0, wr1;

    auto loadA = [&](int k0) {
        if (vec) {
            ar0 = *(const float4*)(A + (size_t)(m0 + arow0) * lda + k0 + aks0 * 4);
            ar1 = *(const float4*)(A + (size_t)(m0 + arow1) * lda + k0 + aks1 * 4);
        } else {
            float v[8];
#pragma unroll
            for (int q = 0; q < 4; q++) {
                int k = k0 + aks0 * 4 + q;
                v[q] = (k < K) ? A[(size_t)(m0 + arow0) * lda + k] : 0.f;
            }
#pragma unroll
            for (int q = 0; q < 4; q++) {
                int k = k0 + aks1 * 4 + q;
                v[4 + q] = (k < K) ? A[(size_t)(m0 + arow1) * lda + k] : 0.f;
            }
            ar0 = make_float4(v[0], v[1], v[2], v[3]);
            ar1 = make_float4(v[4], v[5], v[6], v[7]);
        }
    };
    auto loadW = [&](int k0) {
        if (vec) {
            wr0 = *(const float4*)(W + (size_t)(k0 + wkl0) * ldw + nbase + wn0);
            wr1 = *(const float4*)(W + (size_t)(k0 + wkl1) * ldw + nbase + wn1);
        } else {
            float v[8];
#pragma unroll
            for (int q = 0; q < 4; q++) {
                int k = k0 + wkl0;
                v[q] = (k < K) ? W[(size_t)k * ldw + nbase + wn0 + q] : 0.f;
            }
#pragma unroll
            for (int q = 0; q < 4; q++) {
                int k = k0 + wkl1;
                v[4 + q] = (k < K) ? W[(size_t)k * ldw + nbase + wn1 + q] : 0.f;
            }
            wr0 = make_float4(v[0], v[1], v[2], v[3]);
            wr1 = make_float4(v[4], v[5], v[6], v[7]);
        }
    };
    auto stage = [&]() {
        const bool ri = (flags & 1);
        float a0[4] = {ar0.x, ar0.y, ar0.z, ar0.w};
        float a1[4] = {ar1.x, ar1.y, ar1.z, ar1.w};
#pragma unroll
        for (int q = 0; q < 4; q++) {
            As[aks0 * 4 + q][arow0] = ri ? fmaxf(a0[q], 0.f) : a0[q];
            As[aks1 * 4 + q][arow1] = ri ? fmaxf(a1[q], 0.f) : a1[q];
        }
        *(float4*)&Ws[wkl0][wn0] = wr0;
        *(float4*)&Ws[wkl1][wn1] = wr1;
    };

    ull acc[8][4];
#pragma unroll
    for (int i = 0; i < 8; i++)
#pragma unroll
        for (int j = 0; j < 4; j++) acc[i][j] = 0ull;

    loadA(0);
    loadW(0);

    for (int k0 = 0; k0 < K; k0 += 16) {
        stage();
        __syncthreads();
        if (k0 + 16 < K) { loadA(k0 + 16); loadW(k0 + 16); }

#pragma unroll
        for (int kk = 0; kk < 16; kk++) {
            float4 a0 = *(const float4*)&As[kk][ty * 8];
            float4 a1 = *(const float4*)&As[kk][ty * 8 + 4];
            float4 w0 = *(const float4*)&Ws[kk][tx * 8];
            float4 w1 = *(const float4*)&Ws[kk][tx * 8 + 4];
            ull b0 = pack2(w0.x, w0.y);
            ull b1 = pack2(w0.z, w0.w);
            ull b2 = pack2(w1.x, w1.y);
            ull b3 = pack2(w1.z, w1.w);
            float a[8] = {a0.x, a0.y, a0.z, a0.w, a1.x, a1.y, a1.z, a1.w};
#pragma unroll
            for (int i = 0; i < 8; i++) {
                ull aa = pack2(a[i], a[i]);
                fma2(acc[i][0], aa, b0);
                fma2(acc[i][1], aa, b1);
                fma2(acc[i][2], aa, b2);
                fma2(acc[i][3], aa, b3);
            }
        }
        __syncthreads();
    }

    const int batch = m0 >> 15;  // T = 32768
    float mx[8];
#pragma unroll
    for (int j = 0; j < 8; j++) mx[j] = 0.f;

#pragma unroll
    for (int i = 0; i < 8; i++) {
        const int m = m0 + ty * 8 + i;
#pragma unroll
        for (int j = 0; j < 4; j++) {
            float2 v2 = unpack2(acc[i][j]);
            float v[2] = {v2.x, v2.y};
#pragma unroll
            for (int h = 0; h < 2; h++) {
                const int nl = tx * 8 + 2 * j + h;
                float v1 = v[h];
                if (bias)   v1 += bias[nbase + nl];
                if (addsrc) v1 += addsrc[(size_t)m * ldadd + nl];
                if (bias2)  v1 += bias2[batch * 128 + nl];
                if (flags & 2) v1 = fmaxf(v1, 0.f);
                if (flags & 4) C[(size_t)m * ldc + ccol + nbase + nl] = v1;
                mx[2 * j + h] = fmaxf(mx[2 * j + h], v1);
            }
        }
    }

    if (flags & 8) {
        if (t < 128) smax[t] = 0u;
        __syncthreads();
#pragma unroll
        for (int j = 0; j < 8; j++)
            atomicMax(&smax[tx * 8 + j], __float_as_uint(mx[j]));
        __syncthreads();
        if (t < 128) atomicMax(&colmax[batch * 128 + t], smax[t]);
    }
}

// ---------------- tiny B=8 head: h3, pln_out, change_basis, net_pl ----------------
__global__ void __launch_bounds__(1024)
small_k(const float* __restrict__ h3w, const float* __restrict__ h3b,
        const float* __restrict__ outw, const float* __restrict__ outb,
        const float* __restrict__ hdw,  const float* __restrict__ hdb)
{
    __shared__ float hm[B * 128];
    __shared__ float h3s[B * 128];
    __shared__ float raw[B * 9];

    const int t = threadIdx.x;
    hm[t] = __uint_as_float(g_hmax[t]);
    __syncthreads();

    {   // h3 = relu(hmax @ h3_w + b)
        int b = t >> 7, j = t & 127;
        float acc = h3b[j];
        for (int k = 0; k < 128; k++)
            acc = fmaf(hm[b * 128 + k], h3w[k * 128 + j], acc);
        h3s[t] = fmaxf(acc, 0.f);
    }
    __syncthreads();

    if (t < 72) {   // net_pl_raw = h3 @ pln_out_w + b  (B x 9)
        int b = t / 9, o = t % 9;
        float acc = outb[o];
        for (int k = 0; k < 128; k++)
            acc = fmaf(h3s[b * 128 + k], outw[k * 9 + o], acc);
        raw[t] = acc;
    }
    __syncthreads();

    {   // net_pl = relu(raw) @ plane_hdim_w + b
        int b = t >> 7, j = t & 127;
        float acc = hdb[j];
        for (int o = 0; o < 9; o++)
            acc = fmaf(fmaxf(raw[b * 9 + o], 0.f), hdw[o * 128 + j], acc);
        g_netpl[t] = acc;
    }

    if (t < 24) {   // change_basis per (batch, plane)
        int b = t / 3, l = t % 3;
        float q0 = raw[b * 9 + 3 * l + 0];
        float q1 = raw[b * 9 + 3 * l + 1];
        float q2 = raw[b * 9 + 3 * l + 2];
        float nr = sqrtf(q0 * q0 + q1 * q1 + q2 * q2);
        float n0 = q0 / nr + 1e-6f;
        float n1 = q1 / nr + 1e-6f;
        float n2 = q2 / nr + 1e-6f;
        float v0 = -n1, v1 = n0, v2 = 0.f;
        float S[9] = { 0.f, -v2,  v1,
                       v2,  0.f, -v0,
                      -v1,  v0,  0.f };
        float S2[9];
        for (int i = 0; i < 3; i++)
            for (int j = 0; j < 3; j++) {
                float s = 0.f;
                for (int k = 0; k < 3; k++) s += S[i * 3 + k] * S[k * 3 + j];
                S2[i * 3 + j] = s;
            }
        float coef = (1.f - n2) / (v0 * v0 + v1 * v1 + v2 * v2);
        float R[9];
        for (int i = 0; i < 3; i++)
            for (int j = 0; j < 3; j++)
                R[i * 3 + j] = (i == j ? 1.f : 0.f) + S[i * 3 + j] + S2[i * 3 + j] * coef;
        float c00 =  (R[4] * R[8] - R[5] * R[7]);
        float c01 = -(R[3] * R[8] - R[5] * R[6]);
        float c02 =  (R[3] * R[7] - R[4] * R[6]);
        float det = R[0] * c00 + R[1] * c01 + R[2] * c02;
        float inv[9];
        inv[0] =  c00 / det;
        inv[1] = -(R[1] * R[8] - R[2] * R[7]) / det;
        inv[2] =  (R[1] * R[5] - R[2] * R[4]) / det;
        inv[3] =  c01 / det;
        inv[4] =  (R[0] * R[8] - R[2] * R[6]) / det;
        inv[5] = -(R[0] * R[5] - R[2] * R[3]) / det;
        inv[6] =  c02 / det;
        inv[7] = -(R[0] * R[7] - R[1] * R[6]) / det;
        inv[8] =  (R[0] * R[4] - R[1] * R[3]) / det;
        float bx0 = fabsf(R[0]), bx1 = fabsf(R[3]), bx2 = fabsf(R[6]);
        float by0 = fabsf(R[1]), by1 = fabsf(R[4]), by2 = fabsf(R[7]);
        float sx = bx0 + bx1 + bx2, sx2 = bx0 * bx0 + bx1 * bx1 + bx2 * bx2;
        float sy = by0 + by1 + by2, sy2 = by0 * by0 + by1 * by1 + by2 * by2;
        float nm = fmaxf(sx / sqrtf(sx2), sy / sqrtf(sy2));
        float* o = &g_Cmat[t * 12];
        for (int k = 0; k < 9; k++) o[k] = inv[k];
        o[9] = nm; o[10] = nm; o[11] = nm;
    }
}

// ---------------- per-point plane indices ----------------
__global__ void __launch_bounds__(256)
idx_k(const float* __restrict__ p)
{
    __shared__ float Csh[B * NP * 12];
    const int t = threadIdx.x;
    for (int i = t; i < B * NP * 12; i += 256) Csh[i] = g_Cmat[i];
    __syncthreads();

    const int m = blockIdx.x * 256 + t;
    const float px = p[(size_t)m * 3 + 0];
    const float py = p[(size_t)m * 3 + 1];
    const float pz = p[(size_t)m * 3 + 2];
    const int b = m >> 15;
    const float denom = 1.0f + 0.1f + 0.001f;
#pragma unroll
    for (int l = 0; l < NP; l++) {
        const float* C = &Csh[(b * NP + l) * 12];
        float norm = C[9];
        float q0 = (C[0] * px + C[1] * py + C[2] * pz) / norm;
        float q1 = (C[3] * px + C[4] * py + C[5] * pz) / norm;
        float x = q0 / denom + 0.5f;
        float y = q1 / denom + 0.5f;
        x = fminf(fmaxf(x, 0.f), 1.f - 1e-5f);
        y = fminf(fmaxf(y, 0.f), 1.f - 1e-5f);
        int i = min(max((int)(x * (float)RESO), 0), RESO - 1);
        int j = min(max((int)(y * (float)RESO), 0), RESO - 1);
        g_idx[l * M + m] = i + RESO * j;
    }
}

// ---------------- pooling: scatter-max / gather ----------------
__global__ void __launch_bounds__(256)
scatter_max_k()
{
    const int m = blockIdx.x * 2 + (threadIdx.x >> 7);
    const int c = threadIdx.x & 127;
    const float v = g_x256[(size_t)m * 256 + c];
    const unsigned fv = ford(v);
    const int b = m >> 15;
#pragma unroll
    for (int l = 0; l < NP; l++) {
        int idx = g_idx[l * M + m];
        atomicMax(&g_bins[(((size_t)((b * NP + l) * R2 + idx)) << 7) + c], fv);
    }
}

// vectorized gather: each thread handles 2 channels (uint2)
__global__ void __launch_bounds__(256)
gather_k()
{
    const int m  = blockIdx.x * 4 + (threadIdx.x >> 6);
    const int c2 = threadIdx.x & 63;          // channel pair index
    const int b  = m >> 15;
    float s0 = 0.f, s1 = 0.f;
#pragma unroll
    for (int l = 0; l < NP; l++) {
        int idx = g_idx[l * M + m];
        uint2 w = *(const uint2*)&g_bins[(((size_t)((b * NP + l) * R2 + idx)) << 7) + c2 * 2];
        s0 += iford(w.x);
        s1 += iford(w.y);
    }
    *(float2*)&g_x256[(size_t)m * 256 + 128 + c2 * 2] = make_float2(s0, s1);
}

// ---------------- final plane features ----------------
__global__ void __launch_bounds__(256)
scatter_add_k()
{
    const int m = blockIdx.x * 2 + (threadIdx.x >> 7);
    const int c = threadIdx.x & 127;
    const float v = g_tmp[(size_t)m * 128 + c];
    const int b = m >> 15;
    float* binsf = (float*)g_bins;
#pragma unroll
    for (int l = 0; l < NP; l++) {
        int idx = g_idx[l * M + m];
        atomicAdd(&binsf[(((size_t)((b * NP + l) * R2 + idx)) << 7) + c], v);
    }
    if (c < NP) {
        int idx = g_idx[c * M + m];
        atomicAdd((float*)&g_cnt[(b * NP + c) * R2 + idx], 1.f);
    }
}

__global__ void __launch_bounds__(256)
finalize_k(float* __restrict__ out)
{
    __shared__ float tile[32][129];
    const int blk = blockIdx.x;
    const int pl = blk >> 7;
    const int r0 = (blk & 127) << 5;
    const int t = threadIdx.x;
    const float* binsf = (const float*)g_bins;
#pragma unroll
    for (int i = 0; i < 16; i++) {
        int idx = t + i * 256;
        int rl = idx >> 7, c = idx & 127;
        int r2 = r0 + rl;
        float cnt = __uint_as_float(g_cnt[pl * R2 + r2]);
        tile[rl][c] = binsf[((size_t)pl * R2 + r2) * 128 + c] / fmaxf(cnt, 1.f);
    }
    __syncthreads();
#pragma unroll
    for (int i = 0; i < 16; i++) {
        int idx = t + i * 256;
        int c = idx >> 5, rl = idx & 31;
        out[((size_t)pl * 128 + c) * R2 + r0 + rl] = tile[rl][c];
    }
}

__global__ void copy_cmat_k(float* __restrict__ out)
{
    int t = threadIdx.x;
    if (t < B * NP * 12) out[t] = g_Cmat[t];
}

// ---------------- driver ----------------
extern "C" void kernel_launch(void* const* d_in, const int* in_sizes, int n_in,
                              void* d_out, int out_size)
{
    const float* p        = (const float*)d_in[0];
    const float* pln_in_w = (const float*)d_in[1];
    const float* pln_in_b = (const float*)d_in[2];
    const float* h1w      = (const float*)d_in[3];
    const float* h1b      = (const float*)d_in[4];
    const float* h2w      = (const float*)d_in[5];
    const float* h2b      = (const float*)d_in[6];
    const float* h3w      = (const float*)d_in[7];
    const float* h3b      = (const float*)d_in[8];
    const float* outw     = (const float*)d_in[9];
    const float* outb     = (const float*)d_in[10];
    const float* hdw      = (const float*)d_in[11];
    const float* hdb      = (const float*)d_in[12];
    const float* fcposw   = (const float*)d_in[13];
    const float* fcposb   = (const float*)d_in[14];
    const float* fc0w     = (const float*)d_in[15];
    const float* fc0b     = (const float*)d_in[16];
    const float* fc1w     = (const float*)d_in[17];
    const float* fc1b     = (const float*)d_in[18];
    const float* scw      = (const float*)d_in[19];
    const float* fccw     = (const float*)d_in[20];
    const float* fccb     = (const float*)d_in[21];
    float* out = (float*)d_out;

    float *tmp = nullptr, *dx = nullptr, *x256 = nullptr, *netpl = nullptr;
    unsigned *hmax = nullptr, *bins = nullptr, *cnt = nullptr;
    cudaGetSymbolAddress((void**)&tmp,   g_tmp);
    cudaGetSymbolAddress((void**)&dx,    g_dx);
    cudaGetSymbolAddress((void**)&x256,  g_x256);
    cudaGetSymbolAddress((void**)&netpl, g_netpl);
    cudaGetSymbolAddress((void**)&hmax,  g_hmax);
    cudaGetSymbolAddress((void**)&bins,  g_bins);
    cudaGetSymbolAddress((void**)&cnt,   g_cnt);

    unsigned NEG;
    { float f = -1e30f; unsigned u; memcpy(&u, &f, 4); NEG = ~u; }

    const dim3 gB(M / 128, 1);
    const int GEMM_T = 256;

    // ---- stage 1: point MLP + per-batch column max ----
    linear3_k<128><<<M / 2, 256>>>(p, pln_in_w, pln_in_b, tmp, 1);
    gemm_k<<<gB, GEMM_T>>>(tmp, 128, 128, h1w, 128, h1b,
                           nullptr, 0, nullptr, dx, 128, 0, nullptr, 2 | 4, 1);
    fill_k<<<1, 256>>>(hmax, 0u, (size_t)B * 128);
    gemm_k<<<gB, GEMM_T>>>(dx, 128, 128, h2w, 128, h2b,
                           nullptr, 0, nullptr, nullptr, 0, 0, hmax, 2 | 8, 1);

    // ---- tiny head + plane indices ----
    small_k<<<1, 1024>>>(h3w, h3b, outw, outb, hdw, hdb);
    idx_k<<<M / 256, 256>>>(p);

    // ---- fc_pos: p -> 256-wide net, stored in x256 ----
    linear3_k<256><<<M, 256>>>(p, fcposw, fcposb, x256, 0);

    // ---- residual blocks ----
    auto run_block = [&](int i) {
        gemm_k<<<gB, GEMM_T>>>(x256, 256, 256, fc0w + (size_t)i * 256 * 128, 128,
                               fc0b + i * 128, nullptr, 0, nullptr,
                               tmp, 128, 0, nullptr, 1 | 4, 1);
        gemm_k<<<gB, GEMM_T>>>(tmp, 128, 128, fc1w + (size_t)i * 128 * 128, 128,
                               fc1b + i * 128, nullptr, 0, nullptr,
                               dx, 128, 0, nullptr, 1 | 4, 1);
        gemm_k<<<gB, GEMM_T>>>(x256, 256, 256, scw + (size_t)i * 256 * 128, 128,
                               nullptr, dx, 128, nullptr,
                               x256, 256, 0, nullptr, 4, 1);
    };

    run_block(0);
    for (int i = 1; i < 5; i++) {
        fill_k<<<(int)(NBINS / 4 / 256), 256>>>(bins, NEG, NBINS);
        scatter_max_k<<<M / 2, 256>>>();
        gather_k<<<M / 4, 256>>>();
        run_block(i);
    }

    // ---- c = net @ fc_c + b + net_pl[batch] ----
    gemm_k<<<gB, GEMM_T>>>(x256, 256, 128, fccw, 128, fccb,
                           nullptr, 0, netpl, tmp, 128, 0, nullptr, 4, 1);

    // ---- plane features (mean grids) ----
    fill_k<<<(int)(NBINS / 4 / 256), 256>>>(bins, 0u, NBINS);
    fill_k<<<(int)(NCNT / 4 / 256), 256>>>(cnt, 0u, NCNT);
    scatter_add_k<<<M / 2, 256>>>();
    finalize_k<<<B * NP * (R2 / 32), 256>>>(out);

    // ---- C_mat tail ----
    copy_cmat_k<<<1, 288>>>(out + (size_t)out_size - B * NP * 12);
}